// round 17
// baseline (speedup 1.0000x reference)
#include <cuda_runtime.h>
#include <cstdint>

#define GRID_N 25
#define NN 625
#define RTOT 320000          // 512*625 rows
#define FIN 66
#define DOUT 64
#define TILEM 256            // rows per CTA
#define NTILES (RTOT/TILEM)  // 1250
#define THREADS 256
#define XSTR 68              // padded x smem stride (bank = 4*gid+tig, conflict-free)
#define BSTR 72              // padded B smem stride (bank = 8*tig+gid, conflict-free)

// dynamic smem layout (32-bit words)
#define OFF_BH   0                        // [72][72] u32 tf32-hi image = 5184
#define OFF_BL   5184                     // [72][72] u32 tf32-lo image = 5184
#define OFF_UV   10368                    // 128 floats (W_at)
#define OFF_BIAS 10496                    // 64 floats (b_fc)
#define OFF_X    10560                    // 256*68 + 8 pad = 17416 floats
#define SMEM_WORDS (OFF_X + TILEM*XSTR + 8)   // 27976 words = 111904 B

// ---- device scratch ----
__device__ float g_a1[RTOT];
__device__ float g_a2[RTOT];

__device__ __forceinline__ uint32_t tf32hi(float x){
    uint32_t r; asm("cvt.rna.tf32.f32 %0, %1;" : "=r"(r) : "f"(x)); return r;
}
__device__ __forceinline__ void mma_tf32(float* d,
    uint32_t a0, uint32_t a1, uint32_t a2, uint32_t a3,
    uint32_t b0, uint32_t b1)
{
    asm volatile(
        "mma.sync.aligned.m16n8k8.row.col.f32.tf32.tf32.f32 "
        "{%0,%1,%2,%3}, {%4,%5,%6,%7}, {%8,%9}, {%0,%1,%2,%3};"
        : "+f"(d[0]), "+f"(d[1]), "+f"(d[2]), "+f"(d[3])
        : "r"(a0), "r"(a1), "r"(a2), "r"(a3), "r"(b0), "r"(b1));
}

// ---- Kernel 1: tf32-split MMA GEMM + fused epilogue (W split done in-CTA) ----
__global__ __launch_bounds__(THREADS, 2)
void gemm_kernel(const float* __restrict__ x,
                 const float* __restrict__ Wfc,
                 const float* __restrict__ bfc,
                 const float* __restrict__ Wat,
                 const float* __restrict__ bat,
                 float* __restrict__ hout)
{
    extern __shared__ float sm[];
    uint32_t* sBH  = (uint32_t*)(sm + OFF_BH);
    uint32_t* sBL  = (uint32_t*)(sm + OFF_BL);
    float* sUV     = sm + OFF_UV;
    float* sBias   = sm + OFF_BIAS;
    float* sX      = sm + OFF_X;

    const int tid  = threadIdx.x;
    const int warp = tid >> 5, lane = tid & 31;
    const int gid  = lane >> 2, tig = lane & 3;

    // ---- Phase 0: stage Wfc (64x66 f32) into X region as temp (coalesced) ----
    {
        const float4* wg = (const float4*)Wfc;
        float4* wt = (float4*)sX;
        for (int i = tid; i < (DOUT*FIN)/4; i += THREADS) wt[i] = wg[i];  // 1056 f4
    }
    if (tid < 128) sUV[tid] = Wat[tid];
    if (tid < DOUT) sBias[tid] = bfc[tid];
    __syncthreads();

    // ---- Phase 1: build B hi/lo tf32 images [k][n], stride 72, zero-padded ----
    for (int i = tid; i < BSTR*BSTR; i += THREADS){
        int k = i / BSTR, n = i - k*BSTR;
        float w = (k < FIN && n < DOUT) ? sX[n*FIN + k] : 0.f;
        uint32_t hb = tf32hi(w);
        sBH[i] = hb;
        sBL[i] = tf32hi(w - __uint_as_float(hb));
    }
    __syncthreads();

    // ---- Phase 2: stage x tile (256 rows x 66) into stride-68 rows ----
    {
        const float2* xg = (const float2*)(x + (size_t)blockIdx.x*(TILEM*FIN));
        float2* xs = (float2*)sX;
        #pragma unroll 4
        for (int i = tid; i < TILEM*(FIN/2); i += THREADS){   // 8448 float2
            int row = i / (FIN/2), c = i - row*(FIN/2);
            xs[row*(XSTR/2) + c] = xg[i];
        }
    }
    // zero pad cols 66,67 of every row + 8-float tail (NaN safety for k>=66 reads)
    sX[tid*XSTR + 66] = 0.f;
    sX[tid*XSTR + 67] = 0.f;
    if (tid < 8) sX[TILEM*XSTR + tid] = 0.f;
    __syncthreads();

    // ---- Phase 3: mainloop ----
    float acc[16][4];                          // [mt*8+nt][4]
    #pragma unroll
    for (int t = 0; t < 16; t++){
        acc[t][0]=0.f; acc[t][1]=0.f; acc[t][2]=0.f; acc[t][3]=0.f;
    }

    const float* xw = sX + warp*32*XSTR;       // this warp's 32 rows

    #pragma unroll 3
    for (int ks = 0; ks < 9; ks++){
        const int k0 = ks*8;
        uint32_t Ahi[2][4], Alo[2][4];
        #pragma unroll
        for (int mt = 0; mt < 2; mt++){
            const float* xr = xw + (mt*16 + gid)*XSTR + k0 + tig;
            float a0 = xr[0];
            float a1 = xr[8*XSTR];
            float a2 = xr[4];
            float a3 = xr[8*XSTR + 4];
            Ahi[mt][0] = tf32hi(a0); Alo[mt][0] = tf32hi(a0 - __uint_as_float(Ahi[mt][0]));
            Ahi[mt][1] = tf32hi(a1); Alo[mt][1] = tf32hi(a1 - __uint_as_float(Ahi[mt][1]));
            Ahi[mt][2] = tf32hi(a2); Alo[mt][2] = tf32hi(a2 - __uint_as_float(Ahi[mt][2]));
            Ahi[mt][3] = tf32hi(a3); Alo[mt][3] = tf32hi(a3 - __uint_as_float(Ahi[mt][3]));
        }
        #pragma unroll
        for (int nt = 0; nt < 8; nt++){
            const int bi = (k0 + tig)*BSTR + nt*8 + gid;
            uint32_t bh0 = sBH[bi], bh1 = sBH[bi + 4*BSTR];
            uint32_t bl0 = sBL[bi], bl1 = sBL[bi + 4*BSTR];
            #pragma unroll
            for (int mt = 0; mt < 2; mt++){
                float* d = acc[mt*8 + nt];
                mma_tf32(d, Ahi[mt][0], Ahi[mt][1], Ahi[mt][2], Ahi[mt][3], bh0, bh1);
                mma_tf32(d, Ahi[mt][0], Ahi[mt][1], Ahi[mt][2], Ahi[mt][3], bl0, bl1);
                mma_tf32(d, Alo[mt][0], Alo[mt][1], Alo[mt][2], Alo[mt][3], bh0, bh1);
            }
        }
    }

    // ---- Epilogue: bias, h write, fused a1/a2 dots (quad reduce) ----
    const float batv = bat[0];
    #pragma unroll
    for (int mt = 0; mt < 2; mt++){
        const int r0 = blockIdx.x*TILEM + warp*32 + mt*16 + gid;
        const int r1 = r0 + 8;
        float p1a = 0.f, p2a = 0.f, p1b = 0.f, p2b = 0.f;
        #pragma unroll
        for (int nt = 0; nt < 8; nt++){
            const int col = nt*8 + 2*tig;
            const float u0 = sUV[col],    u1 = sUV[col+1];
            const float v0 = sUV[64+col], v1 = sUV[64+col+1];
            const float bb0 = sBias[col], bb1 = sBias[col+1];
            const float* d = acc[mt*8 + nt];
            float c0 = d[0] + bb0, c1 = d[1] + bb1;   // row r0
            float c2 = d[2] + bb0, c3 = d[3] + bb1;   // row r1
            *(float2*)&hout[(size_t)r0*DOUT + col] = make_float2(c0, c1);
            *(float2*)&hout[(size_t)r1*DOUT + col] = make_float2(c2, c3);
            p1a += c0*u0 + c1*u1;  p2a += c0*v0 + c1*v1;
            p1b += c2*u0 + c3*u1;  p2b += c2*v0 + c3*v1;
        }
        #pragma unroll
        for (int o = 1; o <= 2; o <<= 1){
            p1a += __shfl_xor_sync(0xffffffffu, p1a, o);
            p2a += __shfl_xor_sync(0xffffffffu, p2a, o);
            p1b += __shfl_xor_sync(0xffffffffu, p1b, o);
            p2b += __shfl_xor_sync(0xffffffffu, p2b, o);
        }
        if (tig == 0){
            g_a1[r0] = p1a + batv;  g_a2[r0] = p2a;
            g_a1[r1] = p1b + batv;  g_a2[r1] = p2b;
        }
    }
}

// ---- Kernel 2: 9-way gather + leaky_relu + softmax -> attn_weight ----
__global__ void attn_kernel(float* __restrict__ wout){
    int r = blockIdx.x*blockDim.x + threadIdx.x;
    if (r >= RTOT) return;
    int b  = r / NN;
    int n  = r - b*NN;
    int gr = n / GRID_N;
    int gc = n - gr*GRID_N;
    int rb = gr + (gr == 0) - (gr == GRID_N-1);
    int cb = gc + (gc == 0) - (gc == GRID_N-1);

    float A = g_a1[r];
    const float* a2b = g_a2 + b*NN;

    float s[9];
    #pragma unroll
    for (int k = 0; k < 9; k++){
        int dr = k/3 - 1, dc = k%3 - 1;
        float v = A + a2b[(rb+dr)*GRID_N + (cb+dc)];
        s[k] = (v > 0.f) ? v : 0.01f*v;
    }
    float m = s[0];
    #pragma unroll
    for (int k = 1; k < 9; k++) m = fmaxf(m, s[k]);
    float sum = 0.f;
    #pragma unroll
    for (int k = 0; k < 9; k++){ s[k] = __expf(s[k] - m); sum += s[k]; }
    float inv = 1.0f / sum;
    #pragma unroll
    for (int k = 0; k < 9; k++) wout[(size_t)r*9 + k] = s[k]*inv;
}

extern "C" void kernel_launch(void* const* d_in, const int* in_sizes, int n_in,
                              void* d_out, int out_size)
{
    const float* x   = (const float*)d_in[0];   // [512,625,66]
    const float* Wfc = (const float*)d_in[1];   // [64,66]
    const float* bfc = (const float*)d_in[2];   // [64]
    const float* Wat = (const float*)d_in[3];   // [1,128]
    const float* bat = (const float*)d_in[4];   // [1]
    float* out  = (float*)d_out;
    float* hout = out;                          // attn_vector [512,625,64]
    float* wout = out + (size_t)RTOT*DOUT;      // attn_weight [512,625,9]

    static int smem_set = 0;
    if (!smem_set){
        cudaFuncSetAttribute(gemm_kernel, cudaFuncAttributeMaxDynamicSharedMemorySize,
                             SMEM_WORDS*4);
        smem_set = 1;
    }

    gemm_kernel<<<NTILES, THREADS, SMEM_WORDS*4>>>(x, Wfc, bfc, Wat, bat, hout);
    attn_kernel<<<(RTOT + 255)/256, 256>>>(wout);
}